// round 1
// baseline (speedup 1.0000x reference)
#include <cuda_runtime.h>

#define NB 8
#define NS 2048
#define NE 8
#define NH 2
#define ND 4
#define NT (NB*NS)      // 16384 tokens
#define NBH (NB*NH)     // 16 (batch, head) pairs

// log2(e) / sqrt(D) = log2(e) / 2 folded into q so scores feed ex2 directly
#define QSCALE 0.72134752044448169f

// Scratch (device globals — no allocation allowed). 16B-aligned via float4.
__device__ float4 g_q[NBH*NS];   // [(b*2+h)*S + s]
__device__ float4 g_k[NBH*NS];
__device__ float4 g_v[NBH*NS];
__device__ float4 g_o[NT*2];     // attention out, token-major (2 float4/token)

// ---- packed f32x2 helpers (ptxas won't auto-fuse; PTX only) ----
static __device__ __forceinline__ unsigned long long pack2(float a, float b) {
    unsigned long long r;
    asm("mov.b64 %0, {%1,%2};" : "=l"(r) : "f"(a), "f"(b));
    return r;
}
static __device__ __forceinline__ void unpack2(unsigned long long v, float& a, float& b) {
    asm("mov.b64 {%0,%1}, %2;" : "=f"(a), "=f"(b) : "l"(v));
}
static __device__ __forceinline__ unsigned long long fma2p(unsigned long long a, unsigned long long b, unsigned long long c) {
    unsigned long long d;
    asm("fma.rn.f32x2 %0, %1, %2, %3;" : "=l"(d) : "l"(a), "l"(b), "l"(c));
    return d;
}
static __device__ __forceinline__ unsigned long long mul2p(unsigned long long a, unsigned long long b) {
    unsigned long long d;
    asm("mul.rn.f32x2 %0, %1, %2;" : "=l"(d) : "l"(a), "l"(b));
    return d;
}
static __device__ __forceinline__ float ex2f(float x) {
    float r;
    asm("ex2.approx.f32 %0, %1;" : "=f"(r) : "f"(x));
    return r;
}
static __device__ __forceinline__ float rcpf(float x) {
    float r;
    asm("rcp.approx.f32 %0, %1;" : "=f"(r) : "f"(x));
    return r;
}

// ============================================================
// Kernel A: QKV projection. One thread per token. E=8, trivial.
// q is pre-scaled by log2(e)/sqrt(D).
// ============================================================
__global__ void qkv_kernel(const float* __restrict__ x,
                           const float* __restrict__ Wq,
                           const float* __restrict__ Wk,
                           const float* __restrict__ Wv) {
    int t = blockIdx.x * blockDim.x + threadIdx.x;
    if (t >= NT) return;
    const float4* x4 = (const float4*)x;
    float4 xa = x4[t*2], xb = x4[t*2 + 1];
    float xr[8] = {xa.x, xa.y, xa.z, xa.w, xb.x, xb.y, xb.z, xb.w};
    float q[8], k[8], v[8];
#pragma unroll
    for (int f = 0; f < 8; f++) {
        float sq = 0.f, sk = 0.f, sv = 0.f;
#pragma unroll
        for (int e = 0; e < 8; e++) {
            sq += xr[e] * __ldg(&Wq[f*8 + e]);
            sk += xr[e] * __ldg(&Wk[f*8 + e]);
            sv += xr[e] * __ldg(&Wv[f*8 + e]);
        }
        q[f] = sq * QSCALE; k[f] = sk; v[f] = sv;
    }
    int b = t / NS, s = t % NS;
#pragma unroll
    for (int h = 0; h < NH; h++) {
        int idx = (b*NH + h)*NS + s;
        g_q[idx] = make_float4(q[h*4+0], q[h*4+1], q[h*4+2], q[h*4+3]);
        g_k[idx] = make_float4(k[h*4+0], k[h*4+1], k[h*4+2], k[h*4+3]);
        g_v[idx] = make_float4(v[h*4+0], v[h*4+1], v[h*4+2], v[h*4+3]);
    }
}

// ============================================================
// Kernel B: full-softmax attention, one (b,h) per blockIdx.y,
// 128 queries per CTA (1/thread). K,V (64KB) staged in SMEM.
// Online exp2-sum — scores bounded, no max subtraction needed.
// ============================================================
__global__ void __launch_bounds__(128) attn_kernel() {
    extern __shared__ unsigned char smem_raw[];
    ulonglong2* sK = (ulonglong2*)smem_raw;        // 2048 * 16B
    ulonglong2* sV = sK + NS;                      // 2048 * 16B

    const int bh    = blockIdx.y;
    const int tid   = threadIdx.x;
    const int qi    = blockIdx.x * 128 + tid;

    // cooperative load of K,V for this (b,h)
    const ulonglong2* gk = (const ulonglong2*)(g_k + bh*NS);
    const ulonglong2* gv = (const ulonglong2*)(g_v + bh*NS);
    for (int i = tid; i < NS; i += 128) {
        sK[i] = gk[i];
        sV[i] = gv[i];
    }
    __syncthreads();

    float4 q = g_q[bh*NS + qi];
    const unsigned long long q01 = pack2(q.x, q.y);
    const unsigned long long q23 = pack2(q.z, q.w);

    unsigned long long a01 = pack2(0.f, 0.f);
    unsigned long long a23 = pack2(0.f, 0.f);
    float den = 0.f;

#pragma unroll 8
    for (int j = 0; j < NS; j++) {
        ulonglong2 kk = sK[j];                       // LDS.128 broadcast
        unsigned long long m = mul2p(q23, kk.y);     // {q2k2, q3k3}
        unsigned long long d = fma2p(q01, kk.x, m);  // {q0k0+q2k2, q1k1+q3k3}
        float lo, hi; unpack2(d, lo, hi);
        float w = ex2f(lo + hi);                     // MUFU.EX2
        unsigned long long ww = pack2(w, w);
        ulonglong2 vv = sV[j];                       // LDS.128 broadcast
        a01 = fma2p(ww, vv.x, a01);
        a23 = fma2p(ww, vv.y, a23);
        den += w;
    }

    float r = rcpf(den);
    float o0, o1, o2, o3;
    unpack2(a01, o0, o1);
    unpack2(a23, o2, o3);

    int b = bh >> 1, h = bh & 1;
    g_o[(b*NS + qi)*2 + h] = make_float4(o0*r, o1*r, o2*r, o3*r);
}

// ============================================================
// Kernel C: analytic quantum measurement + Wo.
// z_w = prod_{u<=w} cos(o_u + o_{u&3}) (w>=1); z_0 = prod_{u=1..7}.
// Accurate cosf (args can exceed pi; __cosf error too large for tiny z).
// ============================================================
__global__ void quantum_kernel(const float* __restrict__ Wo,
                               float* __restrict__ out) {
    int t = blockIdx.x * blockDim.x + threadIdx.x;
    if (t >= NT) return;
    float4 oa = g_o[t*2], ob = g_o[t*2 + 1];
    float o[8] = {oa.x, oa.y, oa.z, oa.w, ob.x, ob.y, ob.z, ob.w};
    float c[8];
#pragma unroll
    for (int u = 0; u < 8; u++) c[u] = cosf(o[u] + o[u & 3]);

    float z[8];
    float p = c[0];
#pragma unroll
    for (int w = 1; w < 8; w++) { p *= c[w]; z[w] = p; }
    z[0] = c[1]*c[2]*c[3]*c[4]*c[5]*c[6]*c[7];

    float rr[8];
#pragma unroll
    for (int f = 0; f < 8; f++) {
        float s = 0.f;
#pragma unroll
        for (int qq = 0; qq < 8; qq++) s += z[qq] * __ldg(&Wo[f*8 + qq]);
        rr[f] = s;
    }
    float4* o4 = (float4*)out;
    o4[t*2]     = make_float4(rr[0], rr[1], rr[2], rr[3]);
    o4[t*2 + 1] = make_float4(rr[4], rr[5], rr[6], rr[7]);
}

// ============================================================
extern "C" void kernel_launch(void* const* d_in, const int* in_sizes, int n_in,
                              void* d_out, int out_size) {
    const float* x  = (const float*)d_in[0];
    const float* Wq = (const float*)d_in[1];
    const float* Wk = (const float*)d_in[2];
    const float* Wv = (const float*)d_in[3];
    const float* Wo = (const float*)d_in[4];
    float* out = (float*)d_out;

    qkv_kernel<<<NT/256, 256>>>(x, Wq, Wk, Wv);

    cudaFuncSetAttribute(attn_kernel,
                         cudaFuncAttributeMaxDynamicSharedMemorySize, 65536);
    attn_kernel<<<dim3(NS/128, NBH), 128, 65536>>>();

    quantum_kernel<<<NT/256, 256>>>(Wo, out);
}

// round 2
// speedup vs baseline: 1.5321x; 1.5321x over previous
#include <cuda_runtime.h>

#define NB 8
#define NS 2048
#define NE 8
#define NH 2
#define ND 4
#define NT (NB*NS)       // 16384 tokens
#define NBH (NB*NH)      // 16 (batch, head) pairs
#define SPLITS 4
#define KPS (NS/SPLITS)  // 512 keys per split

// log2(e) / sqrt(D) folded into q so scores feed ex2 directly
#define QSCALE 0.72134752044448169f

// Scratch (device globals — no allocation allowed)
__device__ float4 g_q[NBH*NS];
__device__ float4 g_k[NBH*NS];
__device__ float4 g_v[NBH*NS];
__device__ float4 g_pnum[NBH*SPLITS*NS];   // partial numerators
__device__ float  g_pden[NBH*SPLITS*NS];   // partial denominators

// ---- packed f32x2 helpers ----
static __device__ __forceinline__ unsigned long long pack2(float a, float b) {
    unsigned long long r;
    asm("mov.b64 %0, {%1,%2};" : "=l"(r) : "f"(a), "f"(b));
    return r;
}
static __device__ __forceinline__ void unpack2(unsigned long long v, float& a, float& b) {
    asm("mov.b64 {%0,%1}, %2;" : "=f"(a), "=f"(b) : "l"(v));
}
static __device__ __forceinline__ unsigned long long fma2p(unsigned long long a, unsigned long long b, unsigned long long c) {
    unsigned long long d;
    asm("fma.rn.f32x2 %0, %1, %2, %3;" : "=l"(d) : "l"(a), "l"(b), "l"(c));
    return d;
}
static __device__ __forceinline__ unsigned long long mul2p(unsigned long long a, unsigned long long b) {
    unsigned long long d;
    asm("mul.rn.f32x2 %0, %1, %2;" : "=l"(d) : "l"(a), "l"(b));
    return d;
}
static __device__ __forceinline__ float ex2f(float x) {
    float r;
    asm("ex2.approx.f32 %0, %1;" : "=f"(r) : "f"(x));
    return r;
}
static __device__ __forceinline__ float rcpf(float x) {
    float r;
    asm("rcp.approx.f32 %0, %1;" : "=f"(r) : "f"(x));
    return r;
}

// ============================================================
// Kernel A: QKV projection. Weights staged in SMEM (broadcast
// LDS), 128 threads/CTA, 128 CTAs — full-chip coverage.
// ============================================================
__global__ void __launch_bounds__(128) qkv_kernel(const float* __restrict__ x,
                           const float* __restrict__ Wq,
                           const float* __restrict__ Wk,
                           const float* __restrict__ Wv) {
    __shared__ float sWq[64], sWk[64], sWv[64];
    int tid = threadIdx.x;
    if (tid < 64) {
        sWq[tid] = Wq[tid];
        sWk[tid] = Wk[tid];
        sWv[tid] = Wv[tid];
    }
    __syncthreads();

    int t = blockIdx.x * 128 + tid;
    const float4* x4 = (const float4*)x;
    float4 xa = x4[t*2], xb = x4[t*2 + 1];
    float xr[8] = {xa.x, xa.y, xa.z, xa.w, xb.x, xb.y, xb.z, xb.w};
    float q[8], k[8], v[8];
#pragma unroll
    for (int f = 0; f < 8; f++) {
        float sq = 0.f, sk = 0.f, sv = 0.f;
#pragma unroll
        for (int e = 0; e < 8; e++) {
            sq += xr[e] * sWq[f*8 + e];
            sk += xr[e] * sWk[f*8 + e];
            sv += xr[e] * sWv[f*8 + e];
        }
        q[f] = sq * QSCALE; k[f] = sk; v[f] = sv;
    }
    int b = t / NS, s = t % NS;
#pragma unroll
    for (int h = 0; h < NH; h++) {
        int idx = (b*NH + h)*NS + s;
        g_q[idx] = make_float4(q[h*4+0], q[h*4+1], q[h*4+2], q[h*4+3]);
        g_k[idx] = make_float4(k[h*4+0], k[h*4+1], k[h*4+2], k[h*4+3]);
        g_v[idx] = make_float4(v[h*4+0], v[h*4+1], v[h*4+2], v[h*4+3]);
    }
}

// ============================================================
// Kernel B: split-K softmax attention.
// grid = (NS/128 qblocks, SPLITS, NBH); 128 threads (1 query each).
// Each CTA stages its 512-key K/V slice (16KB) in SMEM.
// Emits per-split partial (num4, den).
// ============================================================
__global__ void __launch_bounds__(128) attn_kernel() {
    __shared__ ulonglong2 sK[KPS];
    __shared__ ulonglong2 sV[KPS];

    const int bh    = blockIdx.z;
    const int split = blockIdx.y;
    const int tid   = threadIdx.x;
    const int qi    = blockIdx.x * 128 + tid;

    const ulonglong2* gk = (const ulonglong2*)(g_k + bh*NS + split*KPS);
    const ulonglong2* gv = (const ulonglong2*)(g_v + bh*NS + split*KPS);
#pragma unroll
    for (int i = 0; i < KPS/128; i++) {
        sK[tid + i*128] = gk[tid + i*128];
        sV[tid + i*128] = gv[tid + i*128];
    }
    __syncthreads();

    float4 q = g_q[bh*NS + qi];
    const unsigned long long q01 = pack2(q.x, q.y);
    const unsigned long long q23 = pack2(q.z, q.w);

    unsigned long long a01 = pack2(0.f, 0.f);
    unsigned long long a23 = pack2(0.f, 0.f);
    float den = 0.f;

#pragma unroll 8
    for (int j = 0; j < KPS; j++) {
        ulonglong2 kk = sK[j];
        unsigned long long m = mul2p(q23, kk.y);
        unsigned long long d = fma2p(q01, kk.x, m);
        float lo, hi; unpack2(d, lo, hi);
        float w = ex2f(lo + hi);
        unsigned long long ww = pack2(w, w);
        ulonglong2 vv = sV[j];
        a01 = fma2p(ww, vv.x, a01);
        a23 = fma2p(ww, vv.y, a23);
        den += w;
    }

    float o0, o1, o2, o3;
    unpack2(a01, o0, o1);
    unpack2(a23, o2, o3);

    int oidx = (bh*SPLITS + split)*NS + qi;
    g_pnum[oidx] = make_float4(o0, o1, o2, o3);
    g_pden[oidx] = den;
}

// ============================================================
// Kernel C: split reduction + analytic quantum measurement + Wo.
// z_w = prod_{u<=w} cos(o_u + o_{u&3}) (w>=1); z_0 = prod_{u=1..7}.
// ============================================================
__global__ void __launch_bounds__(128) quantum_kernel(const float* __restrict__ Wo,
                               float* __restrict__ out) {
    __shared__ float sWo[64];
    int tid = threadIdx.x;
    if (tid < 64) sWo[tid] = Wo[tid];
    __syncthreads();

    int t = blockIdx.x * 128 + tid;
    int b = t / NS, s = t % NS;

    float o[8];
#pragma unroll
    for (int h = 0; h < NH; h++) {
        int bh = b*NH + h;
        float nx = 0.f, ny = 0.f, nz = 0.f, nw = 0.f, den = 0.f;
#pragma unroll
        for (int sp = 0; sp < SPLITS; sp++) {
            int idx = (bh*SPLITS + sp)*NS + s;
            float4 nn = g_pnum[idx];
            nx += nn.x; ny += nn.y; nz += nn.z; nw += nn.w;
            den += g_pden[idx];
        }
        float r = rcpf(den);
        o[h*4+0] = nx*r; o[h*4+1] = ny*r; o[h*4+2] = nz*r; o[h*4+3] = nw*r;
    }

    float c[8];
#pragma unroll
    for (int u = 0; u < 8; u++) c[u] = cosf(o[u] + o[u & 3]);

    float z[8];
    float p = c[0];
#pragma unroll
    for (int w = 1; w < 8; w++) { p *= c[w]; z[w] = p; }
    z[0] = c[1]*c[2]*c[3]*c[4]*c[5]*c[6]*c[7];

    float rr[8];
#pragma unroll
    for (int f = 0; f < 8; f++) {
        float sacc = 0.f;
#pragma unroll
        for (int qq = 0; qq < 8; qq++) sacc += z[qq] * sWo[f*8 + qq];
        rr[f] = sacc;
    }
    float4* o4 = (float4*)out;
    o4[t*2]     = make_float4(rr[0], rr[1], rr[2], rr[3]);
    o4[t*2 + 1] = make_float4(rr[4], rr[5], rr[6], rr[7]);
}

// ============================================================
extern "C" void kernel_launch(void* const* d_in, const int* in_sizes, int n_in,
                              void* d_out, int out_size) {
    const float* x  = (const float*)d_in[0];
    const float* Wq = (const float*)d_in[1];
    const float* Wk = (const float*)d_in[2];
    const float* Wv = (const float*)d_in[3];
    const float* Wo = (const float*)d_in[4];
    float* out = (float*)d_out;

    qkv_kernel<<<NT/128, 128>>>(x, Wq, Wk, Wv);
    attn_kernel<<<dim3(NS/128, SPLITS, NBH), 128>>>();
    quantum_kernel<<<NT/128, 128>>>(Wo, out);
}

// round 3
// speedup vs baseline: 1.7590x; 1.1481x over previous
#include <cuda_runtime.h>

#define NB 8
#define NS 2048
#define NE 8
#define NH 2
#define ND 4
#define NT (NB*NS)        // 16384 tokens
#define NBH (NB*NH)       // 16 (batch, head) pairs
#define SPLITS 8
#define KPS (NS/SPLITS)   // 256 keys per split
#define QB 256            // queries per CTA (2 per thread)

// log2(e) / sqrt(D) folded into q so scores feed ex2 directly
#define QSCALE 0.72134752044448169f

// Scratch (device globals — no allocation allowed)
__device__ float4 g_pnum[NBH*SPLITS*NS];   // partial numerators
__device__ float  g_pden[NBH*SPLITS*NS];   // partial denominators

typedef unsigned long long ull;

// ---- packed f32x2 helpers ----
static __device__ __forceinline__ ull pack2(float a, float b) {
    ull r; asm("mov.b64 %0, {%1,%2};" : "=l"(r) : "f"(a), "f"(b)); return r;
}
static __device__ __forceinline__ void unpack2(ull v, float& a, float& b) {
    asm("mov.b64 {%0,%1}, %2;" : "=f"(a), "=f"(b) : "l"(v));
}
static __device__ __forceinline__ ull fma2p(ull a, ull b, ull c) {
    ull d; asm("fma.rn.f32x2 %0, %1, %2, %3;" : "=l"(d) : "l"(a), "l"(b), "l"(c)); return d;
}
static __device__ __forceinline__ ull mul2p(ull a, ull b) {
    ull d; asm("mul.rn.f32x2 %0, %1, %2;" : "=l"(d) : "l"(a), "l"(b)); return d;
}
static __device__ __forceinline__ float ex2f(float x) {
    float r; asm("ex2.approx.f32 %0, %1;" : "=f"(r) : "f"(x)); return r;
}
static __device__ __forceinline__ float rcpf(float x) {
    float r; asm("rcp.approx.f32 %0, %1;" : "=f"(r) : "f"(x)); return r;
}

// ============================================================
// Kernel B: fused QKV + split-K softmax attention.
// grid = (NS/QB, SPLITS, NBH), 128 threads.
// Each CTA:
//   - stages Wq/Wk/Wv (this head's rows) in SMEM
//   - computes K,V for its 256-key slice from x, K stored
//     lane-duplicated {k0,k0,k1,k1 | k2,k2,k3,k3}
//   - each thread owns 2 queries (computed from x inline);
//     scores for both queries ride one f32x2 lane pair.
// Emits per-split partial (num4, den).
// ============================================================
__global__ void __launch_bounds__(128) attn_kernel(const float* __restrict__ x,
                                                   const float* __restrict__ Wq,
                                                   const float* __restrict__ Wk,
                                                   const float* __restrict__ Wv) {
    __shared__ float sWq[32], sWk[32], sWv[32];   // this head's 4 rows (4x8)
    __shared__ ulonglong2 sK[2*KPS];              // duplicated K: 8KB
    __shared__ ulonglong2 sV[KPS];                // 4KB

    const int bh    = blockIdx.z;
    const int split = blockIdx.y;
    const int tid   = threadIdx.x;
    const int b     = bh >> 1;
    const int h     = bh & 1;

    if (tid < 32) {
        // rows f = h*4 .. h*4+3 of each weight (32 floats)
        sWq[tid] = Wq[h*32 + tid];
        sWk[tid] = Wk[h*32 + tid];
        sWv[tid] = Wv[h*32 + tid];
    }
    __syncthreads();

    const float4* x4 = (const float4*)x;

    // ---- stage K,V slice: 2 keys per thread ----
#pragma unroll
    for (int i = 0; i < KPS/128; i++) {
        int key = tid + i*128;
        int tok = b*NS + split*KPS + key;
        float4 xa = x4[tok*2], xb = x4[tok*2+1];
        float xr[8] = {xa.x, xa.y, xa.z, xa.w, xb.x, xb.y, xb.z, xb.w};
        float k[4], v[4];
#pragma unroll
        for (int d = 0; d < 4; d++) {
            float sk = 0.f, sv = 0.f;
#pragma unroll
            for (int e = 0; e < 8; e++) {
                sk += xr[e] * sWk[d*8 + e];
                sv += xr[e] * sWv[d*8 + e];
            }
            k[d] = sk; v[d] = sv;
        }
        ulonglong2 kd0, kd1, vv;
        kd0.x = pack2(k[0], k[0]); kd0.y = pack2(k[1], k[1]);
        kd1.x = pack2(k[2], k[2]); kd1.y = pack2(k[3], k[3]);
        vv.x  = pack2(v[0], v[1]); vv.y  = pack2(v[2], v[3]);
        sK[2*key]   = kd0;
        sK[2*key+1] = kd1;
        sV[key]     = vv;
    }

    // ---- compute this thread's 2 queries (qa = qi, qb = qi+128) ----
    const int qi = blockIdx.x * QB + tid;
    float qa[4], qb[4];
    {
        int ta = b*NS + qi, tb = ta + 128;
        float4 a0 = x4[ta*2], a1 = x4[ta*2+1];
        float4 b0 = x4[tb*2], b1 = x4[tb*2+1];
        float xra[8] = {a0.x,a0.y,a0.z,a0.w,a1.x,a1.y,a1.z,a1.w};
        float xrb[8] = {b0.x,b0.y,b0.z,b0.w,b1.x,b1.y,b1.z,b1.w};
#pragma unroll
        for (int d = 0; d < 4; d++) {
            float sa = 0.f, sb = 0.f;
#pragma unroll
            for (int e = 0; e < 8; e++) {
                float w = sWq[d*8 + e];
                sa += xra[e] * w;
                sb += xrb[e] * w;
            }
            qa[d] = sa * QSCALE; qb[d] = sb * QSCALE;
        }
    }
    __syncthreads();

    // packed {qa_d, qb_d}
    const ull q0p = pack2(qa[0], qb[0]);
    const ull q1p = pack2(qa[1], qb[1]);
    const ull q2p = pack2(qa[2], qb[2]);
    const ull q3p = pack2(qa[3], qb[3]);
    const ull ONE2 = pack2(1.f, 1.f);

    ull a01a = 0, a23a = 0, a01b = 0, a23b = 0, dp = 0;
    // (bit pattern 0 == {0.f,0.f})

#pragma unroll 4
    for (int j = 0; j < KPS; j++) {
        ulonglong2 kA = sK[2*j];       // {k0,k0 | k1,k1}
        ulonglong2 kB = sK[2*j+1];     // {k2,k2 | k3,k3}
        ull s = mul2p(q0p, kA.x);
        s = fma2p(q1p, kA.y, s);
        s = fma2p(q2p, kB.x, s);
        s = fma2p(q3p, kB.y, s);       // s = {score_a, score_b}
        float sa, sb; unpack2(s, sa, sb);
        float wa = ex2f(sa), wb = ex2f(sb);
        ull wwa = pack2(wa, wa);
        ull wwb = pack2(wb, wb);
        ull wab = pack2(wa, wb);
        ulonglong2 vv = sV[j];
        a01a = fma2p(wwa, vv.x, a01a);
        a23a = fma2p(wwa, vv.y, a23a);
        a01b = fma2p(wwb, vv.x, a01b);
        a23b = fma2p(wwb, vv.y, a23b);
        dp   = fma2p(wab, ONE2, dp);   // {den_a, den_b}
    }

    float n0,n1,n2,n3,m0,m1,m2,m3,da,db;
    unpack2(a01a, n0, n1); unpack2(a23a, n2, n3);
    unpack2(a01b, m0, m1); unpack2(a23b, m2, m3);
    unpack2(dp, da, db);

    int base = (bh*SPLITS + split)*NS + qi;
    g_pnum[base]       = make_float4(n0, n1, n2, n3);
    g_pden[base]       = da;
    g_pnum[base + 128] = make_float4(m0, m1, m2, m3);
    g_pden[base + 128] = db;
}

// ============================================================
// Kernel C: split reduction + analytic quantum measurement + Wo.
// z_w = prod_{u<=w} cos(o_u + o_{u&3}) (w>=1); z_0 = prod_{u=1..7}.
// ============================================================
__global__ void __launch_bounds__(128) quantum_kernel(const float* __restrict__ Wo,
                                                      float* __restrict__ out) {
    __shared__ float sWo[64];
    int tid = threadIdx.x;
    if (tid < 64) sWo[tid] = Wo[tid];
    __syncthreads();

    int t = blockIdx.x * 128 + tid;
    int b = t / NS, s = t % NS;

    float o[8];
#pragma unroll
    for (int h = 0; h < NH; h++) {
        int bh = b*NH + h;
        float nx = 0.f, ny = 0.f, nz = 0.f, nw = 0.f, den = 0.f;
#pragma unroll
        for (int sp = 0; sp < SPLITS; sp++) {
            int idx = (bh*SPLITS + sp)*NS + s;
            float4 nn = g_pnum[idx];
            nx += nn.x; ny += nn.y; nz += nn.z; nw += nn.w;
            den += g_pden[idx];
        }
        float r = rcpf(den);
        o[h*4+0] = nx*r; o[h*4+1] = ny*r; o[h*4+2] = nz*r; o[h*4+3] = nw*r;
    }

    float c[8];
#pragma unroll
    for (int u = 0; u < 8; u++) c[u] = cosf(o[u] + o[u & 3]);

    float z[8];
    float p = c[0];
#pragma unroll
    for (int w = 1; w < 8; w++) { p *= c[w]; z[w] = p; }
    z[0] = c[1]*c[2]*c[3]*c[4]*c[5]*c[6]*c[7];

    float rr[8];
#pragma unroll
    for (int f = 0; f < 8; f++) {
        float sacc = 0.f;
#pragma unroll
        for (int qq = 0; qq < 8; qq++) sacc += z[qq] * sWo[f*8 + qq];
        rr[f] = sacc;
    }
    float4* o4 = (float4*)out;
    o4[t*2]     = make_float4(rr[0], rr[1], rr[2], rr[3]);
    o4[t*2 + 1] = make_float4(rr[4], rr[5], rr[6], rr[7]);
}

// ============================================================
extern "C" void kernel_launch(void* const* d_in, const int* in_sizes, int n_in,
                              void* d_out, int out_size) {
    const float* x  = (const float*)d_in[0];
    const float* Wq = (const float*)d_in[1];
    const float* Wk = (const float*)d_in[2];
    const float* Wv = (const float*)d_in[3];
    const float* Wo = (const float*)d_in[4];
    float* out = (float*)d_out;

    attn_kernel<<<dim3(NS/QB, SPLITS, NBH), 128>>>(x, Wq, Wk, Wv);
    quantum_kernel<<<NT/128, 128>>>(Wo, out);
}

// round 4
// speedup vs baseline: 1.8499x; 1.0517x over previous
#include <cuda_runtime.h>

#define NB 8
#define NS 2048
#define NE 8
#define NH 2
#define ND 4
#define NT (NB*NS)        // 16384 tokens
#define NBH (NB*NH)       // 16 (batch, head) pairs
#define SPLITS 8
#define KPS (NS/SPLITS)   // 256 keys per split
#define NPAIR (KPS/2)     // 128 key pairs
#define QB 256            // queries per CTA (2 per thread)

// log2(e) / sqrt(D) folded into q so scores feed ex2 directly
#define QSCALE 0.72134752044448169f

// Scratch (device globals — no allocation allowed)
__device__ float4 g_pnum[NBH*SPLITS*NS];   // partial numerators
__device__ float  g_pden[NBH*SPLITS*NS];   // partial denominators

typedef unsigned long long ull;

// ---- packed f32x2 helpers ----
static __device__ __forceinline__ ull pack2(float a, float b) {
    ull r; asm("mov.b64 %0, {%1,%2};" : "=l"(r) : "f"(a), "f"(b)); return r;
}
static __device__ __forceinline__ void unpack2(ull v, float& a, float& b) {
    asm("mov.b64 {%0,%1}, %2;" : "=f"(a), "=f"(b) : "l"(v));
}
static __device__ __forceinline__ ull fma2p(ull a, ull b, ull c) {
    ull d; asm("fma.rn.f32x2 %0, %1, %2, %3;" : "=l"(d) : "l"(a), "l"(b), "l"(c)); return d;
}
static __device__ __forceinline__ ull mul2p(ull a, ull b) {
    ull d; asm("mul.rn.f32x2 %0, %1, %2;" : "=l"(d) : "l"(a), "l"(b)); return d;
}
static __device__ __forceinline__ float ex2f(float x) {
    float r; asm("ex2.approx.f32 %0, %1;" : "=f"(r) : "f"(x)); return r;
}
static __device__ __forceinline__ float rcpf(float x) {
    float r; asm("rcp.approx.f32 %0, %1;" : "=f"(r) : "f"(x)); return r;
}

// ============================================================
// Fused QKV + split-K softmax attention.
// grid = (NS/QB, SPLITS, NBH), 128 threads, occ-7 single wave.
// K/V staged key-pair-packed (SoA, conflict-free):
//   sK01[p] = { {k0[2p],k0[2p+1]}, {k1[2p],k1[2p+1]} } etc.
// Each thread: 2 queries x 2 keys per inner iteration
//   -> 18 fma2 + 4 mufu + 4 mov + 4 lds per 4 (q,k) pairs.
// ============================================================
__global__ void __launch_bounds__(128, 7) attn_kernel(const float* __restrict__ x,
                                                      const float* __restrict__ Wq,
                                                      const float* __restrict__ Wk,
                                                      const float* __restrict__ Wv) {
    __shared__ float sWq[32], sWk[32], sWv[32];   // this head's 4 rows (4x8)
    __shared__ ulonglong2 sK01[NPAIR];
    __shared__ ulonglong2 sK23[NPAIR];
    __shared__ ulonglong2 sV01[NPAIR];
    __shared__ ulonglong2 sV23[NPAIR];

    const int bh    = blockIdx.z;
    const int split = blockIdx.y;
    const int tid   = threadIdx.x;
    const int b     = bh >> 1;
    const int h     = bh & 1;

    if (tid < 32) {
        sWq[tid] = Wq[h*32 + tid];
        sWk[tid] = Wk[h*32 + tid];
        sWv[tid] = Wv[h*32 + tid];
    }
    __syncthreads();

    const float4* x4 = (const float4*)x;

    // ---- stage one key pair per thread (keys 2*tid, 2*tid+1) ----
    {
        int tokA = b*NS + split*KPS + 2*tid;
        float4 a0 = x4[tokA*2], a1 = x4[tokA*2+1];
        float4 b0 = x4[tokA*2+2], b1 = x4[tokA*2+3];
        float xra[8] = {a0.x,a0.y,a0.z,a0.w,a1.x,a1.y,a1.z,a1.w};
        float xrb[8] = {b0.x,b0.y,b0.z,b0.w,b1.x,b1.y,b1.z,b1.w};
        float kA[4], vA[4], kB[4], vB[4];
#pragma unroll
        for (int d = 0; d < 4; d++) {
            float ka = 0.f, va = 0.f, kb = 0.f, vb = 0.f;
#pragma unroll
            for (int e = 0; e < 8; e++) {
                float wk = sWk[d*8 + e], wv = sWv[d*8 + e];
                ka += xra[e] * wk;  va += xra[e] * wv;
                kb += xrb[e] * wk;  vb += xrb[e] * wv;
            }
            kA[d] = ka; vA[d] = va; kB[d] = kb; vB[d] = vb;
        }
        ulonglong2 t;
        t.x = pack2(kA[0], kB[0]); t.y = pack2(kA[1], kB[1]); sK01[tid] = t;
        t.x = pack2(kA[2], kB[2]); t.y = pack2(kA[3], kB[3]); sK23[tid] = t;
        t.x = pack2(vA[0], vB[0]); t.y = pack2(vA[1], vB[1]); sV01[tid] = t;
        t.x = pack2(vA[2], vB[2]); t.y = pack2(vA[3], vB[3]); sV23[tid] = t;
    }

    // ---- this thread's 2 queries (qa = qi, qb = qi+128), {q,q}-packed ----
    const int qi = blockIdx.x * QB + tid;
    ull qa[4], qb[4];
    {
        int ta = b*NS + qi, tb = ta + 128;
        float4 a0 = x4[ta*2], a1 = x4[ta*2+1];
        float4 b0 = x4[tb*2], b1 = x4[tb*2+1];
        float xra[8] = {a0.x,a0.y,a0.z,a0.w,a1.x,a1.y,a1.z,a1.w};
        float xrb[8] = {b0.x,b0.y,b0.z,b0.w,b1.x,b1.y,b1.z,b1.w};
#pragma unroll
        for (int d = 0; d < 4; d++) {
            float sa = 0.f, sb = 0.f;
#pragma unroll
            for (int e = 0; e < 8; e++) {
                float w = sWq[d*8 + e];
                sa += xra[e] * w;
                sb += xrb[e] * w;
            }
            qa[d] = pack2(sa * QSCALE, sa * QSCALE);
            qb[d] = pack2(sb * QSCALE, sb * QSCALE);
        }
    }
    __syncthreads();

    const ull ONE2 = pack2(1.f, 1.f);
    ull na0 = 0, na1 = 0, na2 = 0, na3 = 0;   // query a numerators (key-pair lanes)
    ull nb0 = 0, nb1 = 0, nb2 = 0, nb3 = 0;   // query b
    ull dap = 0, dbp = 0;                     // denominators (key-pair lanes)

#pragma unroll 4
    for (int j = 0; j < NPAIR; j++) {
        ulonglong2 kA = sK01[j];     // {k0 pair | k1 pair}
        ulonglong2 kB = sK23[j];     // {k2 pair | k3 pair}
        ull sa = mul2p(qa[0], kA.x);
        ull sb = mul2p(qb[0], kA.x);
        sa = fma2p(qa[1], kA.y, sa);
        sb = fma2p(qb[1], kA.y, sb);
        sa = fma2p(qa[2], kB.x, sa);
        sb = fma2p(qb[2], kB.x, sb);
        sa = fma2p(qa[3], kB.y, sa);  // {score_a(2j), score_a(2j+1)}
        sb = fma2p(qb[3], kB.y, sb);
        float s0, s1, s2, s3;
        unpack2(sa, s0, s1);
        unpack2(sb, s2, s3);
        ull wa = pack2(ex2f(s0), ex2f(s1));
        ull wb = pack2(ex2f(s2), ex2f(s3));
        ulonglong2 vA = sV01[j];
        ulonglong2 vB = sV23[j];
        na0 = fma2p(wa, vA.x, na0);
        na1 = fma2p(wa, vA.y, na1);
        na2 = fma2p(wa, vB.x, na2);
        na3 = fma2p(wa, vB.y, na3);
        nb0 = fma2p(wb, vA.x, nb0);
        nb1 = fma2p(wb, vA.y, nb1);
        nb2 = fma2p(wb, vB.x, nb2);
        nb3 = fma2p(wb, vB.y, nb3);
        dap = fma2p(wa, ONE2, dap);
        dbp = fma2p(wb, ONE2, dbp);
    }

    // horizontal reduce key-pair lanes
    float lo, hi, x0, x1, x2, x3, y0, y1, y2, y3, da, db;
    unpack2(na0, lo, hi); x0 = lo + hi;
    unpack2(na1, lo, hi); x1 = lo + hi;
    unpack2(na2, lo, hi); x2 = lo + hi;
    unpack2(na3, lo, hi); x3 = lo + hi;
    unpack2(nb0, lo, hi); y0 = lo + hi;
    unpack2(nb1, lo, hi); y1 = lo + hi;
    unpack2(nb2, lo, hi); y2 = lo + hi;
    unpack2(nb3, lo, hi); y3 = lo + hi;
    unpack2(dap, lo, hi); da = lo + hi;
    unpack2(dbp, lo, hi); db = lo + hi;

    int base = (bh*SPLITS + split)*NS + qi;
    g_pnum[base]       = make_float4(x0, x1, x2, x3);
    g_pden[base]       = da;
    g_pnum[base + 128] = make_float4(y0, y1, y2, y3);
    g_pden[base + 128] = db;
}

// ============================================================
// Split reduction + analytic quantum measurement + Wo.
// One thread per (token, head); lane pairs (2k,2k+1) share a
// token and exchange via shfl_xor(1). Fast __cosf (RRO+MUFU).
// z_w = prod_{u<=w} cos(o_u + o_{u&3}) (w>=1); z_0 = prod_{u=1..7}.
// ============================================================
__global__ void __launch_bounds__(128) quantum_kernel(const float* __restrict__ Wo,
                                                      float* __restrict__ out) {
    __shared__ float sWo[64];
    int tid = threadIdx.x;
    if (tid < 64) sWo[tid] = Wo[tid];
    __syncthreads();

    int gid = blockIdx.x * 128 + tid;   // 0 .. 32767
    int t = gid >> 1;
    int h = gid & 1;
    int b = t / NS, s = t % NS;
    int bh = b*NH + h;

    float nx = 0.f, ny = 0.f, nz = 0.f, nw = 0.f, den = 0.f;
#pragma unroll
    for (int sp = 0; sp < SPLITS; sp++) {
        int idx = (bh*SPLITS + sp)*NS + s;
        float4 nn = g_pnum[idx];
        nx += nn.x; ny += nn.y; nz += nn.z; nw += nn.w;
        den += g_pden[idx];
    }
    float r = rcpf(den);
    float o0 = nx*r, o1 = ny*r, o2 = nz*r, o3 = nw*r;   // this head's 4 dims

    // other head's o (lane pair exchange)
    float p0 = __shfl_xor_sync(0xFFFFFFFFu, o0, 1);
    float p1 = __shfl_xor_sync(0xFFFFFFFFu, o1, 1);
    float p2 = __shfl_xor_sync(0xFFFFFFFFu, o2, 1);
    float p3 = __shfl_xor_sync(0xFFFFFFFFu, o3, 1);

    // c_u for this thread's u = h*4+d: arg = o_u + o_{u&3}
    //   h=0: o_d + o_d ; h=1: o_d(own, global u=4+d) + head0's o_d (=p_d)
    float a0 = o0 + (h ? p0 : o0);
    float a1 = o1 + (h ? p1 : o1);
    float a2 = o2 + (h ? p2 : o2);
    float a3 = o3 + (h ? p3 : o3);
    float c0 = __cosf(a0), c1 = __cosf(a1), c2 = __cosf(a2), c3 = __cosf(a3);

    // gather all 8 c's
    float q0 = __shfl_xor_sync(0xFFFFFFFFu, c0, 1);
    float q1 = __shfl_xor_sync(0xFFFFFFFFu, c1, 1);
    float q2 = __shfl_xor_sync(0xFFFFFFFFu, c2, 1);
    float q3 = __shfl_xor_sync(0xFFFFFFFFu, c3, 1);
    float gc[8];
    gc[0] = h ? q0 : c0;  gc[1] = h ? q1 : c1;
    gc[2] = h ? q2 : c2;  gc[3] = h ? q3 : c3;
    gc[4] = h ? c0 : q0;  gc[5] = h ? c1 : q1;
    gc[6] = h ? c2 : q2;  gc[7] = h ? c3 : q3;

    // z products
    float z[8];
    float tp = gc[1];
    z[1] = gc[0] * tp;
#pragma unroll
    for (int w = 2; w < 8; w++) { tp *= gc[w]; z[w] = gc[0] * tp; }
    z[0] = tp;

    // this thread's 4 output features f = h*4+i
    float rr[4];
#pragma unroll
    for (int i = 0; i < 4; i++) {
        float sacc = 0.f;
#pragma unroll
        for (int qq = 0; qq < 8; qq++) sacc += z[qq] * sWo[(h*4 + i)*8 + qq];
        rr[i] = sacc;
    }
    ((float4*)out)[t*2 + h] = make_float4(rr[0], rr[1], rr[2], rr[3]);
}

// ============================================================
extern "C" void kernel_launch(void* const* d_in, const int* in_sizes, int n_in,
                              void* d_out, int out_size) {
    const float* x  = (const float*)d_in[0];
    const float* Wq = (const float*)d_in[1];
    const float* Wk = (const float*)d_in[2];
    const float* Wv = (const float*)d_in[3];
    const float* Wo = (const float*)d_in[4];
    float* out = (float*)d_out;

    attn_kernel<<<dim3(NS/QB, SPLITS, NBH), 128>>>(x, Wq, Wk, Wv);
    quantum_kernel<<<NT*NH/128, 128>>>(Wo, out);
}